// round 16
// baseline (speedup 1.0000x reference)
#include <cuda_runtime.h>
#include <cuda_bf16.h>
#include <math.h>
#include <stdint.h>

#define ENT   9
#define INNER 64
#define BB    16
#define SS    512
#define HH    768
#define ND    (ENT * INNER * 2)   // 1152
#define NEG_INF_F 1000000000000.0f

#define N_PROJ_TILES 576          // 9 heads x 64 mblocks
#define TICKETS_PER_HEAD 576      // 64 proj + 192 stores + 320 qk
#define N_TICKETS (9 * TICKETS_PER_HEAD)

__device__ __nv_bfloat16 g_xb[BB * SS * HH];
__device__ __nv_bfloat16 g_wb[HH * ND];
__device__ __nv_bfloat16 g_q[BB * ENT * SS * INNER];
__device__ __nv_bfloat16 g_k[BB * ENT * SS * INNER];
__device__ float g_rope[SS * 64];
__device__ int g_ticket;
__device__ int g_flags[N_PROJ_TILES];

__device__ __forceinline__ uint32_t smem_u32(const void* p) {
    return (uint32_t)__cvta_generic_to_shared(p);
}
__device__ __forceinline__ uint32_t pk_bf2(float lo, float hi) {
    uint32_t r; asm("cvt.rn.bf16x2.f32 %0, %1, %2;" : "=r"(r) : "f"(hi), "f"(lo)); return r;
}
__device__ __forceinline__ void ldsm4(uint32_t* r, uint32_t addr) {
    asm volatile("ldmatrix.sync.aligned.m8n8.x4.shared.b16 {%0,%1,%2,%3}, [%4];"
        : "=r"(r[0]), "=r"(r[1]), "=r"(r[2]), "=r"(r[3]) : "r"(addr));
}
__device__ __forceinline__ void ldsm4t(uint32_t* r, uint32_t addr) {
    asm volatile("ldmatrix.sync.aligned.m8n8.x4.trans.shared.b16 {%0,%1,%2,%3}, [%4];"
        : "=r"(r[0]), "=r"(r[1]), "=r"(r[2]), "=r"(r[3]) : "r"(addr));
}
__device__ __forceinline__ void mma_bf16(float* c, const uint32_t* a, uint32_t b0, uint32_t b1) {
    asm volatile("mma.sync.aligned.m16n8k16.row.col.f32.bf16.bf16.f32 "
        "{%0,%1,%2,%3}, {%4,%5,%6,%7}, {%8,%9}, {%0,%1,%2,%3};"
        : "+f"(c[0]), "+f"(c[1]), "+f"(c[2]), "+f"(c[3])
        : "r"(a[0]), "r"(a[1]), "r"(a[2]), "r"(a[3]), "r"(b0), "r"(b1));
}
__device__ __forceinline__ void cp16(uint32_t dst, const void* src) {
    asm volatile("cp.async.cg.shared.global [%0], [%1], 16;" :: "r"(dst), "l"(src));
}
__device__ __forceinline__ void cp_commit() { asm volatile("cp.async.commit_group;"); }
template<int N> __device__ __forceinline__ void cp_wait() {
    asm volatile("cp.async.wait_group %0;" :: "n"(N));
}

// ---------------------------------------------------------------------------
// Prep: bf16 convert + rope table + scheduler reset.
// ---------------------------------------------------------------------------
__global__ __launch_bounds__(256) void convert_kernel(
    const float* __restrict__ X, const float* __restrict__ W)
{
    const int xq = (BB * SS * HH) / 4;   // 1572864
    const int wq = (HH * ND) / 4;        //  221184
    int i = blockIdx.x * blockDim.x + threadIdx.x;
    if (i < xq) {
        float4 v = *reinterpret_cast<const float4*>(X + 4 * (size_t)i);
        uint2 p = make_uint2(pk_bf2(v.x, v.y), pk_bf2(v.z, v.w));
        *reinterpret_cast<uint2*>(g_xb + 4 * (size_t)i) = p;
    } else if (i < xq + wq) {
        int j = i - xq;
        float4 v = *reinterpret_cast<const float4*>(W + 4 * (size_t)j);
        uint2 p = make_uint2(pk_bf2(v.x, v.y), pk_bf2(v.z, v.w));
        *reinterpret_cast<uint2*>(g_wb + 4 * (size_t)j) = p;
    } else {
        int j = i - xq - wq;
        if (j < SS * 32) {
            int s = j >> 5, p = j & 31;
            float freq = exp2f(-0.41524101186092f * (float)p);
            float sn, cs;
            sincosf((float)s * freq, &sn, &cs);
            g_rope[2 * j]     = cs;
            g_rope[2 * j + 1] = sn;
        } else {
            int j2 = j - SS * 32;
            if (j2 < N_PROJ_TILES) g_flags[j2] = 0;
            else if (j2 == N_PROJ_TILES) g_ticket = 0;
        }
    }
}

// ---------------------------------------------------------------------------
// Fused worker kernel: ticket-scheduled proj / masked-store / qk blocks.
// Tickets per head h: [0,64) proj, [64,256) stores, [256,576) qk.
// ---------------------------------------------------------------------------
#define A_ST 72
#define B_ST 136
#define A_BUF_B (128 * A_ST * 2)   // 18432
#define B_BUF_B (64 * B_ST * 2)    // 17408
#define SMEM_BYTES (2 * A_BUF_B + 2 * B_BUF_B)   // 71680
#define Q_ST 72

__global__ __launch_bounds__(256, 2) void fused_kernel(
    const float* __restrict__ bias,   // [1152]
    const float* __restrict__ mask,   // [16, 512]
    float* __restrict__ out)          // [16, 9, 512, 512]
{
    extern __shared__ __align__(16) char smem[];
    __shared__ int s_ticket;
    const int tid  = threadIdx.x;
    const int lane = tid & 31;
    const int w    = tid >> 5;

    for (;;) {
        if (tid == 0) s_ticket = atomicAdd(&g_ticket, 1);
        __syncthreads();
        const int ticket = s_ticket;
        __syncthreads();
        if (ticket >= N_TICKETS) return;

        const int h = ticket / TICKETS_PER_HEAD;
        const int t = ticket % TICKETS_PER_HEAD;

        if (t < 64) {
            // ---------------- proj tile: (head h, mblock t) ----------------
            const int m0 = t * 128;
            const int n0 = h * 128;
            const uint32_t asA = smem_u32(smem);
            const uint32_t asB = asA + 2 * A_BUF_B;
            const int wm = w >> 2, wn = w & 3;

            float acc[4][4][4];
            #pragma unroll
            for (int i = 0; i < 4; i++)
                #pragma unroll
                for (int j = 0; j < 4; j++)
                    #pragma unroll
                    for (int r = 0; r < 4; r++) acc[i][j][r] = 0.f;

            const int ar0 = tid >> 3, ac0 = (tid & 7) * 8;
            const int br0 = tid >> 4, bc0 = (tid & 15) * 8;

            const uint32_t aoff = (uint32_t)((wm * 64 + (lane & 15)) * A_ST + (lane >> 4) * 8) * 2;
            const uint32_t boff = (uint32_t)((((lane >> 3) & 1) * 8 + (lane & 7)) * B_ST
                                             + wn * 32 + ((lane >> 4) & 1) * 8) * 2;

            // stage k-chunk 0
            #pragma unroll
            for (int i = 0; i < 4; i++) {
                const int r = ar0 + i * 32;
                cp16(asA + (uint32_t)(r * A_ST + ac0) * 2,
                     g_xb + (size_t)(m0 + r) * HH + ac0);
            }
            #pragma unroll
            for (int i = 0; i < 4; i++) {
                const int r = br0 + i * 16;
                cp16(asB + (uint32_t)(r * B_ST + bc0) * 2,
                     g_wb + (size_t)r * ND + n0 + bc0);
            }
            cp_commit();

            const int NT = HH / 64;   // 12
            for (int tt = 0; tt < NT; tt++) {
                const int buf = tt & 1;
                if (tt < NT - 1) {
                    const int k0 = (tt + 1) * 64;
                    const uint32_t aB = asA + (uint32_t)(buf ^ 1) * A_BUF_B;
                    const uint32_t bB = asB + (uint32_t)(buf ^ 1) * B_BUF_B;
                    #pragma unroll
                    for (int i = 0; i < 4; i++) {
                        const int r = ar0 + i * 32;
                        cp16(aB + (uint32_t)(r * A_ST + ac0) * 2,
                             g_xb + (size_t)(m0 + r) * HH + k0 + ac0);
                    }
                    #pragma unroll
                    for (int i = 0; i < 4; i++) {
                        const int r = br0 + i * 16;
                        cp16(bB + (uint32_t)(r * B_ST + bc0) * 2,
                             g_wb + (size_t)(k0 + r) * ND + n0 + bc0);
                    }
                    cp_commit(); cp_wait<1>();
                } else {
                    cp_wait<0>();
                }
                __syncthreads();

                const uint32_t abase = asA + (uint32_t)buf * A_BUF_B;
                const uint32_t bbase = asB + (uint32_t)buf * B_BUF_B;
                #pragma unroll
                for (int ks = 0; ks < 4; ks++) {
                    uint32_t a[4][4], b[2][4];
                    #pragma unroll
                    for (int i = 0; i < 4; i++)
                        ldsm4(a[i], abase + aoff + (uint32_t)(i * 16 * A_ST + ks * 16) * 2);
                    #pragma unroll
                    for (int jp = 0; jp < 2; jp++)
                        ldsm4t(b[jp], bbase + boff + (uint32_t)(ks * 16 * B_ST) * 2 + jp * 32);
                    #pragma unroll
                    for (int i = 0; i < 4; i++)
                        #pragma unroll
                        for (int j = 0; j < 4; j++)
                            mma_bf16(acc[i][j], a[i], b[j >> 1][(j & 1) * 2], b[j >> 1][(j & 1) * 2 + 1]);
                }
                __syncthreads();
            }

            // epilogue: bias + RoPE, bf16 scatter
            #pragma unroll
            for (int j = 0; j < 4; j++) {
                const int n = n0 + wn * 32 + j * 8 + (lane & 3) * 2;
                const int wloc = n & 127;
                const bool is_q = (wloc < 64);
                const int d = wloc & 63;
                const float b0f = __ldg(&bias[n]);
                const float b1f = __ldg(&bias[n + 1]);
                __nv_bfloat16* dst = is_q ? g_q : g_k;
                #pragma unroll
                for (int i = 0; i < 4; i++) {
                    #pragma unroll
                    for (int hh = 0; hh < 2; hh++) {
                        const int m = m0 + wm * 64 + i * 16 + (lane >> 2) + hh * 8;
                        const int bb = m >> 9;
                        const int s  = m & 511;
                        const float2 r2 = *reinterpret_cast<const float2*>(&g_rope[s * 64 + d]);
                        const float v0 = acc[i][j][2 * hh]     + b0f;
                        const float v1 = acc[i][j][2 * hh + 1] + b1f;
                        const int base = (((bb * ENT + h) * SS) + s) * INNER + d;
                        *reinterpret_cast<uint32_t*>(&dst[base]) =
                            pk_bf2(v0 * r2.x - v1 * r2.y, v1 * r2.x + v0 * r2.y);
                    }
                }
            }
            __threadfence();
            __syncthreads();
            if (tid == 0) atomicExch(&g_flags[h * 64 + t], 1);

        } else if (t < 256) {
            // ---------------- masked store block ----------------
            const int s = t - 64;                 // 0..191
            const int b = s / 12, blk = s % 12;
            int my, nx;
            if (blk < 2)      { my = 1; nx = blk; }
            else if (blk < 6) { my = 2; nx = blk - 2; }
            else              { my = 3; nx = blk - 6; }
            const int bz = b * ENT + h;
            const int m0 = my * 128, n0 = nx * 64;
            const int c4 = (tid & 15) * 4;
            const int r0 = tid >> 4;
            const float4 p = *reinterpret_cast<const float4*>(&mask[b * SS + n0 + c4]);
            float4 v;
            v.x = (-(1.0f - p.x) * NEG_INF_F - NEG_INF_F) * 0.125f;
            v.y = (-(1.0f - p.y) * NEG_INF_F - NEG_INF_F) * 0.125f;
            v.z = (-(1.0f - p.z) * NEG_INF_F - NEG_INF_F) * 0.125f;
            v.w = (-(1.0f - p.w) * NEG_INF_F - NEG_INF_F) * 0.125f;
            float* base = &out[((size_t)bz * SS + m0 + r0) * SS + n0 + c4];
            #pragma unroll
            for (int i = 0; i < 8; i++)
                __stcs(reinterpret_cast<float4*>(base + (size_t)i * 16 * SS), v);

        } else {
            // ---------------- qk block ----------------
            const int q = t - 256;                // 0..319
            const int b = q / 20, blk = q % 20;
            int my, nx;
            if (blk < 8)       { my = 0; nx = blk; }
            else if (blk < 14) { my = 1; nx = blk - 6; }
            else if (blk < 18) { my = 2; nx = blk - 10; }
            else               { my = 3; nx = blk - 12; }
            const int bz = b * ENT + h;
            const int m0 = my * 128, n0 = nx * 64;

            // wait for the two producing proj tiles
            if (tid == 0) {
                const int f1 = h * 64 + b * 4 + my;
                const int f2 = h * 64 + b * 4 + (nx >> 1);
                while (atomicAdd(&g_flags[f1], 0) == 0) __nanosleep(64);
                while (atomicAdd(&g_flags[f2], 0) == 0) __nanosleep(64);
            }
            __syncthreads();

            __nv_bfloat16* Qs = reinterpret_cast<__nv_bfloat16*>(smem);
            __nv_bfloat16* Ks = reinterpret_cast<__nv_bfloat16*>(smem + 128 * Q_ST * 2);
            const __nv_bfloat16* Qb = g_q + (size_t)bz * SS * INNER;
            const __nv_bfloat16* Kb = g_k + (size_t)bz * SS * INNER;

            #pragma unroll
            for (int qq = 0; qq < 4; qq++) {
                int v = tid + qq * 256;
                int r = v >> 3, c8 = (v & 7) * 8;
                *reinterpret_cast<uint4*>(&Qs[r * Q_ST + c8]) =
                    *reinterpret_cast<const uint4*>(&Qb[(size_t)(m0 + r) * INNER + c8]);
            }
            #pragma unroll
            for (int qq = 0; qq < 2; qq++) {
                int v = tid + qq * 256;
                int r = v >> 3, c8 = (v & 7) * 8;
                *reinterpret_cast<uint4*>(&Ks[r * Q_ST + c8]) =
                    *reinterpret_cast<const uint4*>(&Kb[(size_t)(n0 + r) * INNER + c8]);
            }
            __syncthreads();

            float acc[2][4][4];
            #pragma unroll
            for (int i = 0; i < 2; i++)
                #pragma unroll
                for (int j = 0; j < 4; j++)
                    #pragma unroll
                    for (int r = 0; r < 4; r++) acc[i][j][r] = 0.f;

            const int wm2 = w >> 1, wn2 = w & 1;
            const uint32_t asQ = smem_u32(Qs);
            const uint32_t asK = smem_u32(Ks);
            const uint32_t aoff = (uint32_t)((wm2 * 32 + (lane & 15)) * Q_ST + (lane >> 4) * 8) * 2;
            const uint32_t boff = (uint32_t)((wn2 * 32 + ((lane >> 4) & 1) * 8 + (lane & 7)) * Q_ST
                                             + ((lane >> 3) & 1) * 8) * 2;

            #pragma unroll
            for (int ks = 0; ks < 4; ks++) {
                uint32_t a[2][4], bfr[2][4];
                #pragma unroll
                for (int i = 0; i < 2; i++)
                    ldsm4(a[i], asQ + aoff + (uint32_t)(i * 16 * Q_ST + ks * 16) * 2);
                #pragma unroll
                for (int jp = 0; jp < 2; jp++)
                    ldsm4(bfr[jp], asK + boff + (uint32_t)(jp * 16 * Q_ST + ks * 16) * 2);
                #pragma unroll
                for (int i = 0; i < 2; i++)
                    #pragma unroll
                    for (int j = 0; j < 4; j++)
                        mma_bf16(acc[i][j], a[i], bfr[j >> 1][(j & 1) * 2], bfr[j >> 1][(j & 1) * 2 + 1]);
            }

            #pragma unroll
            for (int j = 0; j < 4; j++) {
                const int n = n0 + wn2 * 32 + j * 8 + (lane & 3) * 2;
                const float p0 = __ldg(&mask[b * SS + n]);
                const float p1 = __ldg(&mask[b * SS + n + 1]);
                #pragma unroll
                for (int i = 0; i < 2; i++) {
                    #pragma unroll
                    for (int hh = 0; hh < 2; hh++) {
                        const int m = m0 + wm2 * 32 + i * 16 + (lane >> 2) + hh * 8;
                        float lo = acc[i][j][2 * hh]     * p0 - (1.0f - p0) * NEG_INF_F;
                        float hi = acc[i][j][2 * hh + 1] * p1 - (1.0f - p1) * NEG_INF_F;
                        if (m > n)     lo -= NEG_INF_F;
                        if (m > n + 1) hi -= NEG_INF_F;
                        float2 v = make_float2(lo * 0.125f, hi * 0.125f);
                        __stcs(reinterpret_cast<float2*>(&out[((size_t)bz * SS + m) * SS + n]), v);
                    }
                }
            }
        }
    }
}

extern "C" void kernel_launch(void* const* d_in, const int* in_sizes, int n_in,
                              void* d_out, int out_size) {
    const float* X    = (const float*)d_in[0];  // [16,512,768]
    const float* msk  = (const float*)d_in[1];  // [16,512]
    const float* W    = (const float*)d_in[2];  // [768,1152]
    const float* bias = (const float*)d_in[3];  // [1152]
    float* out = (float*)d_out;                 // [16,9,512,512]

    const int cvt_items = (BB * SS * HH + HH * ND) / 4 + SS * 32 + N_PROJ_TILES + 1;
    convert_kernel<<<(cvt_items + 255) / 256, 256>>>(X, W);

    static bool attr_set = false;
    if (!attr_set) {
        cudaFuncSetAttribute(fused_kernel,
                             cudaFuncAttributeMaxDynamicSharedMemorySize, SMEM_BYTES);
        attr_set = true;
    }
    fused_kernel<<<296, 256, SMEM_BYTES>>>(bias, msk, out);
}